// round 11
// baseline (speedup 1.0000x reference)
#include <cuda_runtime.h>
#include <cuda_fp16.h>
#include <cstdint>
#include <cstddef>

// ---------------- problem constants ----------------
#define EMBED   4096
#define RPT     1024
#define NTILES  4
#define OUTF    4096
#define MTOK    8192            // B*S tokens

// ---------------- GEMM tiling ----------------
#define BK 64                   // 64 fp16 = 128B rows -> SW128 swizzle
#define NCHUNK (EMBED / BK)     // 64
#define NTG 128                 // GEMM threads (4 warps)
#define NT  256                 // prep threads
#define NSTAGE 3
#define BMc 128
#define BNc 128
#define STAGE_BYTES ((uint32_t)(BMc + BNc) * 128)   // 32KB
#define SMEM_DYN (NSTAGE * STAGE_BYTES + 1024)      // ~97KB -> 2 CTAs/SM

// warp layout: 4 warps = 2 (M) x 2 (N); warp tile 64x64
#define NMF 4
#define NNF 8
#define WMH 64
#define WNH 64

#define N_DEC  1024             // decode tiles
#define N_LIN  2048             // linear tiles
#define N_ITEM (N_DEC + N_LIN)

// ---------------- device scratch (fp16) ----------------
__device__ __half g_Xh[(size_t)MTOK * EMBED];             // x rounded fp16 (64MB)
__device__ __half g_Ah[(size_t)OUTF * EMBED];             // gathered cw fp16 (32MB)
__device__ __half g_Rh[(size_t)NTILES * EMBED * EMBED];   // R^T single fp16 (128MB)
__device__ __half g_Wh[(size_t)OUTF * EMBED];             // decoded W*256 fp16 (32MB)

// work queue + readiness counters
__device__ int g_queue;
__device__ int g_wready[32];

// ---------------- helpers ----------------
__device__ __forceinline__ uint32_t smem_u32(const void* p) {
    uint32_t a;
    asm("{ .reg .u64 t; cvta.to.shared.u64 t, %1; cvt.u32.u64 %0, t; }" : "=r"(a) : "l"(p));
    return a;
}
__device__ __forceinline__ uint32_t swz(uint32_t b) { return b ^ ((b >> 3) & 0x70); }

__device__ __forceinline__ void ldsm4(uint32_t& r0, uint32_t& r1, uint32_t& r2, uint32_t& r3,
                                      uint32_t addr) {
    asm volatile("ldmatrix.sync.aligned.m8n8.x4.shared.b16 {%0,%1,%2,%3}, [%4];"
                 : "=r"(r0), "=r"(r1), "=r"(r2), "=r"(r3) : "r"(addr));
}
__device__ __forceinline__ void mma16816(float* c, const uint32_t* a, const uint32_t* b) {
    asm volatile(
        "mma.sync.aligned.m16n8k16.row.col.f32.f16.f16.f32 "
        "{%0,%1,%2,%3}, {%4,%5,%6,%7}, {%8,%9}, {%0,%1,%2,%3};"
        : "+f"(c[0]), "+f"(c[1]), "+f"(c[2]), "+f"(c[3])
        : "r"(a[0]), "r"(a[1]), "r"(a[2]), "r"(a[3]), "r"(b[0]), "r"(b[1]));
}
__device__ __forceinline__ void cpasync16(uint32_t dst, const void* src) {
    uint64_t g;
    asm("cvta.to.global.u64 %0, %1;" : "=l"(g) : "l"(src));
    asm volatile("cp.async.cg.shared.global [%0], [%1], 16;" :: "r"(dst), "l"(g));
}
#define CP_COMMIT() asm volatile("cp.async.commit_group;" ::: "memory")
#define CP_WAIT1()  asm volatile("cp.async.wait_group 1;" ::: "memory")

__device__ __forceinline__ uint32_t pack2(__half a, __half b) {
    return (uint32_t)__half_as_ushort(a) | ((uint32_t)__half_as_ushort(b) << 16);
}
__device__ __forceinline__ bool indices_are_i64(const int* __restrict__ p) {
    bool is64 = true;
#pragma unroll
    for (int i = 0; i < 8; ++i) is64 = is64 && (p[2 * i + 1] == 0);
    return is64;
}

// ---------------------------------------------------------------------------
// Prep 1: x -> g_Xh (single fp16); also resets queue + readiness counters.
// ---------------------------------------------------------------------------
__global__ __launch_bounds__(NT)
void conv_x_kernel(const float* __restrict__ x)
{
    if (blockIdx.x == 0 && threadIdx.x < 33) {
        if (threadIdx.x == 0) g_queue = 0;
        else g_wready[threadIdx.x - 1] = 0;
    }
#pragma unroll
    for (int j = 0; j < 4; ++j) {
        size_t f4 = (size_t)blockIdx.x * 1024 + threadIdx.x + j * 256;
        float4 v = *reinterpret_cast<const float4*>(x + f4 * 4);
        uint2 h;
        h.x = pack2(__float2half_rn(v.x), __float2half_rn(v.y));
        h.y = pack2(__float2half_rn(v.z), __float2half_rn(v.w));
        *reinterpret_cast<uint2*>(g_Xh + f4 * 4) = h;
    }
}

// ---------------------------------------------------------------------------
// Prep 2: gather + round codewords -> g_Ah (single fp16)
// ---------------------------------------------------------------------------
__global__ __launch_bounds__(NT)
void gather_kernel(const float* __restrict__ codewords,
                   const int*   __restrict__ idx_raw)
{
    const int b = blockIdx.x;
    const bool is64 = indices_are_i64(idx_raw);
    const int cidx = is64 ? idx_raw[2 * b] : idx_raw[b];
    const float* __restrict__ src = codewords + (size_t)cidx * EMBED;
#pragma unroll
    for (int j = 0; j < 4; ++j) {
        int e4 = threadIdx.x + j * 256;
        float4 v = *reinterpret_cast<const float4*>(src + e4 * 4);
        uint2 h;
        h.x = pack2(__float2half_rn(v.x), __float2half_rn(v.y));
        h.y = pack2(__float2half_rn(v.z), __float2half_rn(v.w));
        *reinterpret_cast<uint2*>(g_Ah + (size_t)b * EMBED + e4 * 4) = h;
    }
}

// ---------------------------------------------------------------------------
// Prep 3: transpose rotations: R[t][d][e] -> g_Rh [t][e][d] single fp16
// ---------------------------------------------------------------------------
__global__ __launch_bounds__(NT)
void transpose_kernel(const float* __restrict__ rot)
{
    __shared__ float sm[32][133];
    const int xb = blockIdx.x;   // e block (128)
    const int yb = blockIdx.y;   // d block (32)
    const int t  = blockIdx.z;
    const int tid = threadIdx.x;

#pragma unroll
    for (int p = 0; p < 4; ++p) {
        int dd = p * 8 + (tid >> 5);
        int e4 = (tid & 31);
        float4 v = *reinterpret_cast<const float4*>(
            rot + ((size_t)t * EMBED + yb * 32 + dd) * EMBED + xb * 128 + e4 * 4);
        sm[dd][e4 * 4 + 0] = v.x;
        sm[dd][e4 * 4 + 1] = v.y;
        sm[dd][e4 * 4 + 2] = v.z;
        sm[dd][e4 * 4 + 3] = v.w;
    }
    __syncthreads();

    const int dg = tid & 3;          // d group (8 d's each)
#pragma unroll
    for (int p = 0; p < 2; ++p) {
        int e = (tid >> 2) + p * 64;
        uint4 w;
        uint32_t* wp = reinterpret_cast<uint32_t*>(&w);
#pragma unroll
        for (int j = 0; j < 4; ++j) {
            float f0 = sm[dg * 8 + 2 * j][e];
            float f1 = sm[dg * 8 + 2 * j + 1][e];
            wp[j] = pack2(__float2half_rn(f0), __float2half_rn(f1));
        }
        size_t o = (size_t)t * EMBED * EMBED + (size_t)(xb * 128 + e) * EMBED
                 + yb * 32 + dg * 8;
        *reinterpret_cast<uint4*>(g_Rh + o) = w;
    }
}

// ---------------------------------------------------------------------------
// Fused persistent GEMM kernel. 128 threads (4 warps 2x2), warp tile 64x64,
// CTA tile 128x128, 3-stage cp.async pipeline, 2 CTAs/SM.
// Work queue items:
//   [0, 1024):   decode tile. id -> rb = id>>5 (W row-block), bn = (id&31)*128.
//                C = cw @ R^T ; g_Wh = fp16(C * scales * 256); signal w_ready[rb].
//   [1024,3072): linear tile. lid -> nb = lid>>6, mb = lid&63.
//                Gated on w_ready[nb]==32. out = (x @ W^T)/256 + bias.
// ---------------------------------------------------------------------------
__global__ __launch_bounds__(NTG, 2)
void gemm_fused(const float* __restrict__ bias, float* __restrict__ out,
                const float* __restrict__ scales)
{
    constexpr uint32_t OFF_A0 = 0;
    constexpr uint32_t OFF_B0 = (uint32_t)BMc * 128;

    extern __shared__ char smraw[];
    const uint32_t sraw = smem_u32(smraw);
    const uint32_t sb   = (sraw + 1023u) & ~1023u;
    __shared__ int s_id;

    const int tid  = threadIdx.x;
    const int wid  = tid >> 5;
    const int lane = tid & 31;
    const int wm   = wid & 1;
    const int wn   = wid >> 1;
    const int k16   = tid & 7;
    const int rbase = tid >> 3;

    for (;;) {
        __syncthreads();                       // protect s_id reuse
        if (tid == 0) s_id = atomicAdd(&g_queue, 1);
        __syncthreads();
        const int id = s_id;
        if (id >= N_ITEM) break;

        const bool dec = (id < N_DEC);
        int bm, bn, blk;
        const __half* __restrict__ A;
        const __half* __restrict__ B;
        if (dec) {
            blk = id >> 5;                     // W row-block
            bn  = (id & 31) << 7;
            bm  = blk << 7;
            A = g_Ah;
            B = g_Rh + ((size_t)(bm >> 10) << 24);   // t * 4096 * 4096
        } else {
            const int lid = id - N_DEC;
            blk = lid >> 6;                    // n-block
            bm  = (lid & 63) << 7;
            bn  = blk << 7;
            A = g_Xh;
            B = g_Wh;
            if (tid == 0) {
                while (atomicAdd(&g_wready[blk], 0) < 32) __nanosleep(64);
            }
            __syncthreads();                   // broadcast acquire to all threads
        }

        float acc[NMF][NNF][4];
#pragma unroll
        for (int i = 0; i < NMF; ++i)
#pragma unroll
            for (int j = 0; j < NNF; ++j)
#pragma unroll
                for (int q = 0; q < 4; ++q) acc[i][j][q] = 0.0f;

        auto issue = [&](int c, int stage) {
            const uint32_t st = sb + (uint32_t)stage * STAGE_BYTES;
            const size_t kofs = (size_t)c * BK + k16 * 8;
#pragma unroll
            for (int i = 0; i < BMc / 16; ++i) {
                const int row = rbase + i * 16;
                const uint32_t d = swz((uint32_t)(row * 128 + k16 * 16));
                cpasync16(st + OFF_A0 + d, A + (size_t)(bm + row) * EMBED + kofs);
            }
#pragma unroll
            for (int i = 0; i < BNc / 16; ++i) {
                const int row = rbase + i * 16;
                const uint32_t d = swz((uint32_t)(row * 128 + k16 * 16));
                cpasync16(st + OFF_B0 + d, B + (size_t)(bn + row) * EMBED + kofs);
            }
        };

        issue(0, 0); CP_COMMIT();
        issue(1, 1); CP_COMMIT();

        int stage = 0;
#pragma unroll 1
        for (int c = 0; c < NCHUNK; ++c) {
            CP_WAIT1();
            __syncthreads();
            if (c + 2 < NCHUNK) issue(c + 2, (stage + 2) % NSTAGE);
            CP_COMMIT();

            const uint32_t st = sb + (uint32_t)stage * STAGE_BYTES;
#pragma unroll
            for (int ks = 0; ks < 4; ++ks) {
                uint32_t b0[NNF * 2];
#pragma unroll
                for (int np = 0; np < NNF / 2; ++np) {
                    const int rB = wn * WNH + np * 16 + (lane & 7) + ((lane >> 4) & 1) * 8;
                    const uint32_t off = swz((uint32_t)(rB * 128 + ks * 32 + ((lane >> 3) & 1) * 16));
                    ldsm4(b0[np * 4 + 0], b0[np * 4 + 1], b0[np * 4 + 2], b0[np * 4 + 3],
                          st + OFF_B0 + off);
                }
#pragma unroll
                for (int mf = 0; mf < NMF; ++mf) {
                    const int rA = wm * WMH + mf * 16 + (lane & 15);
                    const uint32_t off = swz((uint32_t)(rA * 128 + ks * 32 + (lane >> 4) * 16));
                    uint32_t a0[4];
                    ldsm4(a0[0], a0[1], a0[2], a0[3], st + OFF_A0 + off);
#pragma unroll
                    for (int nf = 0; nf < NNF; ++nf)
                        mma16816(acc[mf][nf], a0, &b0[(nf >> 1) * 4 + (nf & 1) * 2]);
                }
            }
            stage = (stage + 1) % NSTAGE;
        }

        // ---- epilogue ----
        if (dec) {
            const float s = scales[bm >> 10] * 256.0f;
#pragma unroll
            for (int nf = 0; nf < NNF; ++nf) {
                const int col = bn + wn * WNH + nf * 8 + (lane & 3) * 2;
#pragma unroll
                for (int mf = 0; mf < NMF; ++mf) {
                    const int row = bm + wm * WMH + mf * 16 + (lane >> 2);
                    uint32_t p0 = pack2(__float2half_rn(acc[mf][nf][0] * s),
                                        __float2half_rn(acc[mf][nf][1] * s));
                    uint32_t p1 = pack2(__float2half_rn(acc[mf][nf][2] * s),
                                        __float2half_rn(acc[mf][nf][3] * s));
                    *reinterpret_cast<uint32_t*>(g_Wh + (size_t)row * EMBED + col)       = p0;
                    *reinterpret_cast<uint32_t*>(g_Wh + (size_t)(row + 8) * EMBED + col) = p1;
                }
            }
            __threadfence();                   // W visible before signaling
            __syncthreads();                   // all threads' stores fenced
            if (tid == 0) atomicAdd(&g_wready[blk], 1);
        } else {
            constexpr float INV = 1.0f / 256.0f;
#pragma unroll
            for (int nf = 0; nf < NNF; ++nf) {
                const int col = bn + wn * WNH + nf * 8 + (lane & 3) * 2;
                const float b0 = bias[col], b1 = bias[col + 1];
#pragma unroll
                for (int mf = 0; mf < NMF; ++mf) {
                    const int row = bm + wm * WMH + mf * 16 + (lane >> 2);
                    float2 v0 = make_float2(acc[mf][nf][0] * INV + b0, acc[mf][nf][1] * INV + b1);
                    float2 v1 = make_float2(acc[mf][nf][2] * INV + b0, acc[mf][nf][3] * INV + b1);
                    *reinterpret_cast<float2*>(out + (size_t)row * OUTF + col)       = v0;
                    *reinterpret_cast<float2*>(out + (size_t)(row + 8) * OUTF + col) = v1;
                }
            }
        }
    }
}

// ---------------------------------------------------------------------------
// Launch. Inputs: x, codewords, indices, rotations, scales, bias.
// ---------------------------------------------------------------------------
extern "C" void kernel_launch(void* const* d_in, const int* in_sizes, int n_in,
                              void* d_out, int out_size)
{
    const float* x         = (const float*)d_in[0];
    const float* codewords = (const float*)d_in[1];
    const int*   indices   = (const int*)  d_in[2];
    const float* rotations = (const float*)d_in[3];
    const float* scales    = (const float*)d_in[4];
    const float* bias      = (const float*)d_in[5];
    float*       out       = (float*)d_out;

    const int M = in_sizes[0] / EMBED;   // 8192
    (void)M;

    static int nsm = 0;
    if (nsm == 0) {
        cudaDeviceGetAttribute(&nsm, cudaDevAttrMultiProcessorCount, 0);
        if (nsm <= 0) nsm = 148;
        cudaFuncSetAttribute(gemm_fused, cudaFuncAttributeMaxDynamicSharedMemorySize, SMEM_DYN);
    }

    // prep (also resets queue/counters each launch)
    conv_x_kernel<<<(size_t)MTOK * EMBED / 4096, NT>>>(x);
    gather_kernel<<<NTILES * RPT, NT>>>(codewords, indices);
    transpose_kernel<<<dim3(EMBED / 128, EMBED / 32, NTILES), NT>>>(rotations);

    // fused decode + linear, persistent workers
    gemm_fused<<<2 * nsm, NTG, SMEM_DYN>>>(bias, out, scales);
}

// round 13
// speedup vs baseline: 1.0441x; 1.0441x over previous
#include <cuda_runtime.h>
#include <cuda_fp16.h>
#include <cstdint>
#include <cstddef>

// ---------------- problem constants ----------------
#define EMBED   4096
#define RPT     1024
#define NTILES  4
#define OUTF    4096
#define MTOK    8192            // B*S tokens

// ---------------- GEMM tiling ----------------
#define BK 64                   // 64 fp16 = 128B rows -> SW128 swizzle
#define NCHUNK (EMBED / BK)     // 64
#define NTG 128                 // GEMM threads (4 warps)
#define NT  256                 // prep threads
#define NSTAGE 3
#define BMc 128
#define BNc 128
#define STAGE_BYTES ((uint32_t)(BMc + BNc) * 128)   // 32KB
#define SMEM_DYN (NSTAGE * STAGE_BYTES + 1024)      // ~97KB -> 2 CTAs/SM

// warp layout: 4 warps = 2 (M) x 2 (N); warp tile 64x64
#define NMF 4
#define NNF 8
#define WMH 64
#define WNH 64

#define N_DEC  1024             // decode tiles
#define N_LIN  2048             // linear tiles

// prep block ranges
#define PB_CONV  8192
#define PB_GATH  4096
#define PB_TRAN  16384          // 4 tiles x 128 d-blocks x 32 e-blocks
#define PB_TOTAL (PB_CONV + PB_GATH + PB_TRAN)

// ---------------- device scratch (fp16) ----------------
__device__ __half g_Xh[(size_t)MTOK * EMBED];             // x rounded fp16 (64MB)
__device__ __half g_Ah[(size_t)OUTF * EMBED];             // gathered cw fp16 (32MB)
__device__ __half g_Rh[(size_t)NTILES * EMBED * EMBED];   // R^T single fp16 (128MB)
__device__ __half g_Wh[(size_t)OUTF * EMBED];             // decoded W*256 fp16 (32MB)

// readiness counters (one per W row-block)
__device__ int g_wready[32];

// ---------------- helpers ----------------
__device__ __forceinline__ uint32_t smem_u32(const void* p) {
    uint32_t a;
    asm("{ .reg .u64 t; cvta.to.shared.u64 t, %1; cvt.u32.u64 %0, t; }" : "=r"(a) : "l"(p));
    return a;
}
__device__ __forceinline__ uint32_t swz(uint32_t b) { return b ^ ((b >> 3) & 0x70); }

__device__ __forceinline__ void ldsm4(uint32_t& r0, uint32_t& r1, uint32_t& r2, uint32_t& r3,
                                      uint32_t addr) {
    asm volatile("ldmatrix.sync.aligned.m8n8.x4.shared.b16 {%0,%1,%2,%3}, [%4];"
                 : "=r"(r0), "=r"(r1), "=r"(r2), "=r"(r3) : "r"(addr));
}
__device__ __forceinline__ void mma16816(float* c, const uint32_t* a, const uint32_t* b) {
    asm volatile(
        "mma.sync.aligned.m16n8k16.row.col.f32.f16.f16.f32 "
        "{%0,%1,%2,%3}, {%4,%5,%6,%7}, {%8,%9}, {%0,%1,%2,%3};"
        : "+f"(c[0]), "+f"(c[1]), "+f"(c[2]), "+f"(c[3])
        : "r"(a[0]), "r"(a[1]), "r"(a[2]), "r"(a[3]), "r"(b[0]), "r"(b[1]));
}
__device__ __forceinline__ void cpasync16(uint32_t dst, const void* src) {
    uint64_t g;
    asm("cvta.to.global.u64 %0, %1;" : "=l"(g) : "l"(src));
    asm volatile("cp.async.cg.shared.global [%0], [%1], 16;" :: "r"(dst), "l"(g));
}
#define CP_COMMIT() asm volatile("cp.async.commit_group;" ::: "memory")
#define CP_WAIT1()  asm volatile("cp.async.wait_group 1;" ::: "memory")

__device__ __forceinline__ uint32_t pack2(__half a, __half b) {
    return (uint32_t)__half_as_ushort(a) | ((uint32_t)__half_as_ushort(b) << 16);
}
__device__ __forceinline__ bool indices_are_i64(const int* __restrict__ p) {
    bool is64 = true;
#pragma unroll
    for (int i = 0; i < 8; ++i) is64 = is64 && (p[2 * i + 1] == 0);
    return is64;
}

// ---------------------------------------------------------------------------
// Unified prep kernel (one launch):
//   blocks [0, 8192):           x -> g_Xh (fp16)
//   blocks [8192, 12288):       gather + round codewords -> g_Ah
//   blocks [12288, 28672):      transpose rotations -> g_Rh [t][e][d]
//   block 0 additionally zeroes g_wready.
// ---------------------------------------------------------------------------
__global__ __launch_bounds__(NT)
void prep_kernel(const float* __restrict__ x,
                 const float* __restrict__ codewords,
                 const int*   __restrict__ idx_raw,
                 const float* __restrict__ rot)
{
    const int b   = blockIdx.x;
    const int tid = threadIdx.x;

    if (b == 0 && tid < 32) g_wready[tid] = 0;

    if (b < PB_CONV) {
        // ---- conv x ----
#pragma unroll
        for (int j = 0; j < 4; ++j) {
            size_t f4 = (size_t)b * 1024 + tid + j * 256;
            float4 v = *reinterpret_cast<const float4*>(x + f4 * 4);
            uint2 h;
            h.x = pack2(__float2half_rn(v.x), __float2half_rn(v.y));
            h.y = pack2(__float2half_rn(v.z), __float2half_rn(v.w));
            *reinterpret_cast<uint2*>(g_Xh + f4 * 4) = h;
        }
    } else if (b < PB_CONV + PB_GATH) {
        // ---- gather codewords ----
        const int r = b - PB_CONV;                // 0..4095
        const bool is64 = indices_are_i64(idx_raw);
        const int cidx = is64 ? idx_raw[2 * r] : idx_raw[r];
        const float* __restrict__ src = codewords + (size_t)cidx * EMBED;
#pragma unroll
        for (int j = 0; j < 4; ++j) {
            int e4 = tid + j * 256;
            float4 v = *reinterpret_cast<const float4*>(src + e4 * 4);
            uint2 h;
            h.x = pack2(__float2half_rn(v.x), __float2half_rn(v.y));
            h.y = pack2(__float2half_rn(v.z), __float2half_rn(v.w));
            *reinterpret_cast<uint2*>(g_Ah + (size_t)r * EMBED + e4 * 4) = h;
        }
    } else {
        // ---- transpose rotations ----
        __shared__ float sm[32][133];
        const int tb = b - PB_CONV - PB_GATH;     // 0..16383
        const int xb = tb & 31;                   // e block (128 wide): 0..31
        const int yb = (tb >> 5) & 127;           // d block (32 wide):  0..127
        const int t  = tb >> 12;                  // tile: 0..3

#pragma unroll
        for (int p = 0; p < 4; ++p) {
            int dd = p * 8 + (tid >> 5);
            int e4 = (tid & 31);
            float4 v = *reinterpret_cast<const float4*>(
                rot + ((size_t)t * EMBED + yb * 32 + dd) * EMBED + xb * 128 + e4 * 4);
            sm[dd][e4 * 4 + 0] = v.x;
            sm[dd][e4 * 4 + 1] = v.y;
            sm[dd][e4 * 4 + 2] = v.z;
            sm[dd][e4 * 4 + 3] = v.w;
        }
        __syncthreads();

        const int dg = tid & 3;                   // d group (8 d's each)
#pragma unroll
        for (int p = 0; p < 2; ++p) {
            int e = (tid >> 2) + p * 64;
            uint4 w;
            uint32_t* wp = reinterpret_cast<uint32_t*>(&w);
#pragma unroll
            for (int j = 0; j < 4; ++j) {
                float f0 = sm[dg * 8 + 2 * j][e];
                float f1 = sm[dg * 8 + 2 * j + 1][e];
                wp[j] = pack2(__float2half_rn(f0), __float2half_rn(f1));
            }
            size_t o = (size_t)t * EMBED * EMBED + (size_t)(xb * 128 + e) * EMBED
                     + yb * 32 + dg * 8;
            *reinterpret_cast<uint4*>(g_Rh + o) = w;
        }
    }
}

// ---------------------------------------------------------------------------
// Fused GEMM, ONE non-persistent launch of 3072 CTAs.
//   blocks [0, 1024):    decode tile. rb = bid>>5, bn = (bid&31)*128, bm = rb*128.
//                        C = cw @ R^T; g_Wh = fp16(C*scale*256); signal w_ready[rb].
//   blocks [1024, 3072): linear tile. lid = bid-1024, nb = lid>>6 (SLOW axis),
//                        mb = lid&63. Gated on w_ready[nb]==32.
// In-order block dispatch: all decode CTAs receive slots before any linear CTA,
// so a gated CTA's producers are always already resident -> no deadlock.
// 128 threads (4 warps 2x2), warp tile 64x64, 3-stage cp.async, 2 CTAs/SM.
// ---------------------------------------------------------------------------
__global__ __launch_bounds__(NTG, 2)
void gemm_all(const float* __restrict__ bias, float* __restrict__ out,
              const float* __restrict__ scales)
{
    constexpr uint32_t OFF_A0 = 0;
    constexpr uint32_t OFF_B0 = (uint32_t)BMc * 128;

    extern __shared__ char smraw[];
    const uint32_t sraw = smem_u32(smraw);
    const uint32_t sb   = (sraw + 1023u) & ~1023u;

    const int tid  = threadIdx.x;
    const int wid  = tid >> 5;
    const int lane = tid & 31;
    const int wm   = wid & 1;
    const int wn   = wid >> 1;
    const int k16   = tid & 7;
    const int rbase = tid >> 3;

    const int id  = blockIdx.x;
    const bool dec = (id < N_DEC);
    int bm, bn, blk;
    const __half* __restrict__ A;
    const __half* __restrict__ B;
    if (dec) {
        blk = id >> 5;                         // W row-block
        bn  = (id & 31) << 7;
        bm  = blk << 7;
        A = g_Ah;
        B = g_Rh + ((size_t)(bm >> 10) << 24); // t * 4096 * 4096
    } else {
        const int lid = id - N_DEC;
        blk = lid >> 6;                        // n-block (slow axis: ready earliest)
        bm  = (lid & 63) << 7;
        bn  = blk << 7;
        A = g_Xh;
        B = g_Wh;
        if (tid == 0) {
            while (atomicAdd(&g_wready[blk], 0) < 32) __nanosleep(128);
            __threadfence();
        }
        __syncthreads();                       // acquire broadcast
    }

    float acc[NMF][NNF][4];
#pragma unroll
    for (int i = 0; i < NMF; ++i)
#pragma unroll
        for (int j = 0; j < NNF; ++j)
#pragma unroll
            for (int q = 0; q < 4; ++q) acc[i][j][q] = 0.0f;

    auto issue = [&](int c, int stage) {
        const uint32_t st = sb + (uint32_t)stage * STAGE_BYTES;
        const size_t kofs = (size_t)c * BK + k16 * 8;
#pragma unroll
        for (int i = 0; i < BMc / 16; ++i) {
            const int row = rbase + i * 16;
            const uint32_t d = swz((uint32_t)(row * 128 + k16 * 16));
            cpasync16(st + OFF_A0 + d, A + (size_t)(bm + row) * EMBED + kofs);
        }
#pragma unroll
        for (int i = 0; i < BNc / 16; ++i) {
            const int row = rbase + i * 16;
            const uint32_t d = swz((uint32_t)(row * 128 + k16 * 16));
            cpasync16(st + OFF_B0 + d, B + (size_t)(bn + row) * EMBED + kofs);
        }
    };

    issue(0, 0); CP_COMMIT();
    issue(1, 1); CP_COMMIT();

    int stage = 0;
#pragma unroll 1
    for (int c = 0; c < NCHUNK; ++c) {
        CP_WAIT1();
        __syncthreads();
        if (c + 2 < NCHUNK) issue(c + 2, (stage + 2) % NSTAGE);
        CP_COMMIT();

        const uint32_t st = sb + (uint32_t)stage * STAGE_BYTES;
#pragma unroll
        for (int ks = 0; ks < 4; ++ks) {
            uint32_t b0[NNF * 2];
#pragma unroll
            for (int np = 0; np < NNF / 2; ++np) {
                const int rB = wn * WNH + np * 16 + (lane & 7) + ((lane >> 4) & 1) * 8;
                const uint32_t off = swz((uint32_t)(rB * 128 + ks * 32 + ((lane >> 3) & 1) * 16));
                ldsm4(b0[np * 4 + 0], b0[np * 4 + 1], b0[np * 4 + 2], b0[np * 4 + 3],
                      st + OFF_B0 + off);
            }
#pragma unroll
            for (int mf = 0; mf < NMF; ++mf) {
                const int rA = wm * WMH + mf * 16 + (lane & 15);
                const uint32_t off = swz((uint32_t)(rA * 128 + ks * 32 + (lane >> 4) * 16));
                uint32_t a0[4];
                ldsm4(a0[0], a0[1], a0[2], a0[3], st + OFF_A0 + off);
#pragma unroll
                for (int nf = 0; nf < NNF; ++nf)
                    mma16816(acc[mf][nf], a0, &b0[(nf >> 1) * 4 + (nf & 1) * 2]);
            }
        }
        stage = (stage + 1) % NSTAGE;
    }

    // ---- epilogue ----
    if (dec) {
        const float s = scales[bm >> 10] * 256.0f;
#pragma unroll
        for (int nf = 0; nf < NNF; ++nf) {
            const int col = bn + wn * WNH + nf * 8 + (lane & 3) * 2;
#pragma unroll
            for (int mf = 0; mf < NMF; ++mf) {
                const int row = bm + wm * WMH + mf * 16 + (lane >> 2);
                uint32_t p0 = pack2(__float2half_rn(acc[mf][nf][0] * s),
                                    __float2half_rn(acc[mf][nf][1] * s));
                uint32_t p1 = pack2(__float2half_rn(acc[mf][nf][2] * s),
                                    __float2half_rn(acc[mf][nf][3] * s));
                *reinterpret_cast<uint32_t*>(g_Wh + (size_t)row * EMBED + col)       = p0;
                *reinterpret_cast<uint32_t*>(g_Wh + (size_t)(row + 8) * EMBED + col) = p1;
            }
        }
        __threadfence();                       // this thread's W stores visible
        __syncthreads();                       // all threads fenced
        if (tid == 0) atomicAdd(&g_wready[blk], 1);
    } else {
        constexpr float INV = 1.0f / 256.0f;
#pragma unroll
        for (int nf = 0; nf < NNF; ++nf) {
            const int col = bn + wn * WNH + nf * 8 + (lane & 3) * 2;
            const float b0 = bias[col], b1 = bias[col + 1];
#pragma unroll
            for (int mf = 0; mf < NMF; ++mf) {
                const int row = bm + wm * WMH + mf * 16 + (lane >> 2);
                float2 v0 = make_float2(acc[mf][nf][0] * INV + b0, acc[mf][nf][1] * INV + b1);
                float2 v1 = make_float2(acc[mf][nf][2] * INV + b0, acc[mf][nf][3] * INV + b1);
                *reinterpret_cast<float2*>(out + (size_t)row * OUTF + col)       = v0;
                *reinterpret_cast<float2*>(out + (size_t)(row + 8) * OUTF + col) = v1;
            }
        }
    }
}

// ---------------------------------------------------------------------------
// Launch. Inputs: x, codewords, indices, rotations, scales, bias.
// ---------------------------------------------------------------------------
extern "C" void kernel_launch(void* const* d_in, const int* in_sizes, int n_in,
                              void* d_out, int out_size)
{
    const float* x         = (const float*)d_in[0];
    const float* codewords = (const float*)d_in[1];
    const int*   indices   = (const int*)  d_in[2];
    const float* rotations = (const float*)d_in[3];
    const float* scales    = (const float*)d_in[4];
    const float* bias      = (const float*)d_in[5];
    float*       out       = (float*)d_out;

    cudaFuncSetAttribute(gemm_all, cudaFuncAttributeMaxDynamicSharedMemorySize, SMEM_DYN);

    // unified prep (also zeroes readiness counters)
    prep_kernel<<<PB_TOTAL, NT>>>(x, codewords, indices, rotations);

    // fused decode + linear, single ordered launch
    gemm_all<<<N_DEC + N_LIN, NTG, SMEM_DYN>>>(bias, out, scales);
}